// round 14
// baseline (speedup 1.0000x reference)
#include <cuda_runtime.h>
#include <cuda_bf16.h>
#include <math_constants.h>
#include <cstdint>

// Problem constants
#define NROWS 8192      // B*H*W = 8*32*32
#define NE    16384
#define KDIM  256
#define NCHUNK 4        // KDIM/64
#define TCM   128       // rows per CTA tile
#define TCN   256       // cols per CTA tile
#define NBLK2 (NE / TCN)    // 64
#define MBLK2 (NROWS / TCM) // 64
#define NZQ   2097152
#define NOUTBLOCKS (NZQ / 256)
#define NSLOT 16
// Screening deviation (bf16 inputs + TC accum, Cauchy-Schwarz): delta <= 1.4e-4.
// Capture needs THR > 2*delta = 2.8e-4 (candidate d kept in f32 -> no store err).
#define RESCREEN_THR 6e-4f

#define SWZ(x) ((x) ^ (((x) >> 3) & 0x70))

// GEMM smem: A chunks (128 rows x 128B) x2, B chunks (256 rows x 128B) x2
#define SMA0 0
#define SMA1 16384
#define SMB0 32768
#define SMB1 65536
// Epilogue aliases (valid after final mainloop sync):
#define EP_ENT   0        // float2 sentry[128][16]  (16KB)
#define EP_MIN   16384    // float  smin[128]
#define EP_CNT   16896    // int    scount[128]
#define EP_SD    17408    // float  sd[128][4]
#define SM_TOTAL 98304

// Scratch (device globals; no allocation allowed)
__device__ float  g_t1[NROWS];
__device__ float  g_pd[NROWS * 64];
__device__ float  g_md[NROWS];            // global TC-min per row
__device__ int    g_idx[NROWS];
__device__ double g_lpart[NOUTBLOCKS];
__device__ __align__(16) __nv_bfloat16 g_Aext[(size_t)NROWS * KDIM];   // 4 MB
__device__ __align__(16) __nv_bfloat16 g_Bext[(size_t)NE * KDIM];      // 8 MB
__device__ __align__(16) float2 g_cand[(size_t)NROWS * NBLK2 * NSLOT]; // 64 MB
__device__ int    g_ccnt[NROWS * NBLK2];                               // 2 MB

// ---------------- PTX helpers (all baseline ISA, legal on plain sm_100) ----
__device__ __forceinline__ uint32_t smem_u32(const void* p) {
    uint32_t a;
    asm("{ .reg .u64 t; cvta.to.shared.u64 t, %1; cvt.u32.u64 %0, t; }" : "=r"(a) : "l"(p));
    return a;
}
__device__ __forceinline__ void cp16(uint32_t d, const void* s) {
    asm volatile("cp.async.cg.shared.global [%0], [%1], 16;" :: "r"(d), "l"(s) : "memory");
}
__device__ __forceinline__ void ldm_x4(uint32_t* r, uint32_t a) {
    asm volatile("ldmatrix.sync.aligned.m8n8.x4.shared.b16 {%0,%1,%2,%3}, [%4];"
                 : "=r"(r[0]), "=r"(r[1]), "=r"(r[2]), "=r"(r[3]) : "r"(a));
}
__device__ __forceinline__ void mma16816(float* c, const uint32_t* a,
                                         uint32_t b0, uint32_t b1) {
    asm volatile(
        "mma.sync.aligned.m16n8k16.row.col.f32.bf16.bf16.f32 "
        "{%0,%1,%2,%3}, {%4,%5,%6,%7}, {%8,%9}, {%0,%1,%2,%3};"
        : "+f"(c[0]), "+f"(c[1]), "+f"(c[2]), "+f"(c[3])
        : "r"(a[0]), "r"(a[1]), "r"(a[2]), "r"(a[3]), "r"(b0), "r"(b1));
}

// ---------------------------------------------------------------------------
// K1: per-row ||z||^2.
// ---------------------------------------------------------------------------
__global__ void k_prep(const float* __restrict__ z) {
    int row = blockIdx.x * blockDim.x + threadIdx.x;
    if (row >= NROWS) return;
    int b  = row >> 10;
    int hw = row & 1023;
    const float* p = z + (size_t)b * 262144 + hw;
    float s = 0.0f;
#pragma unroll 8
    for (int c = 0; c < KDIM; c++) {
        float v = p[(size_t)c * 1024];
        s = fmaf(v, v, s);
    }
    g_t1[row] = s;
}

// ---------------------------------------------------------------------------
// K1b: RN-convert emb to bf16 (screening precision only; rescreen repairs).
// ---------------------------------------------------------------------------
__global__ void k_convB(const float* __restrict__ emb) {
    int t = blockIdx.x * 256 + threadIdx.x;
    if (t >= NE * KDIM) return;
    g_Bext[t] = __float2bfloat16(emb[t]);
}

// ---------------------------------------------------------------------------
// K1c: transpose z to row-major [row][k] and RN-convert to bf16.
// ---------------------------------------------------------------------------
__global__ void k_convA(const float* __restrict__ z) {
    __shared__ float s[32][33];
    int tx = threadIdx.x & 31, ty = threadIdx.x >> 5;
    int hw0 = blockIdx.x * 32, c0 = blockIdx.y * 32, b = blockIdx.z;
    s[ty][tx] = z[(size_t)b * 262144 + (size_t)(c0 + ty) * 1024 + hw0 + tx];
    __syncthreads();
    int r = (b << 10) + hw0 + ty;
    int c = c0 + tx;
    g_Aext[(size_t)r * KDIM + c] = __float2bfloat16(s[tx][ty]);
}

// ---------------------------------------------------------------------------
// K2: mma.sync bf16 screening GEMM. CTA 128x256, 512 threads (16 warps).
// Epilogue: per-(row,tile) min -> g_pd/smem, then in-register threshold scan
// pushes candidates (d_tc <= tile_min + THR) into per-row smem lists
// (atomic order nondeterminism is harmless: final lex-min is set-invariant).
// count > NSLOT => overflow; rescreen recomputes that tile exactly.
// ---------------------------------------------------------------------------
__global__ void __launch_bounds__(512, 1) k_gemm_mma() {
    extern __shared__ char smem[];
    const uint32_t sb = smem_u32(smem);
    const int tid  = threadIdx.x;
    const int lane = tid & 31;
    const int warp = tid >> 5;
    const int wm   = warp >> 2;
    const int wn   = warp & 3;
    const int q    = lane >> 2;
    const int qt   = lane & 3;
    const int nb   = blockIdx.x;
    const int mb   = blockIdx.y;
    const int m0   = mb * TCM;
    const int n0   = nb * TCN;

    const char* Ag = (const char*)(g_Aext + (size_t)m0 * KDIM);
    const char* Bg = (const char*)(g_Bext + (size_t)n0 * KDIM);

    const int a_r  = (lane & 7) + ((lane >> 3) & 1) * 8;
    const int a_kh = lane >> 4;
    const int b_r  = (lane & 7) + ((lane >> 4) & 1) * 8;
    const int b_kh = (lane >> 3) & 1;

    float acc[2][8][4];
#pragma unroll
    for (int mt = 0; mt < 2; mt++)
#pragma unroll
        for (int nt = 0; nt < 8; nt++)
#pragma unroll
            for (int r = 0; r < 4; r++) acc[mt][nt][r] = 0.0f;

    auto load_chunk = [&](int ck, int buf) {
        const int koff = ck * 128;
#pragma unroll
        for (int p = 0; p < 2; p++) {
            int idx = tid + p * 512;
            int row = idx >> 3, g = idx & 7;
            cp16(sb + (buf ? SMA1 : SMA0) + (uint32_t)SWZ(row * 128 + g * 16),
                 Ag + (size_t)row * 512 + koff + g * 16);
        }
#pragma unroll
        for (int p = 0; p < 4; p++) {
            int idx = tid + p * 512;
            int row = idx >> 3, g = idx & 7;
            cp16(sb + (buf ? SMB1 : SMB0) + (uint32_t)SWZ(row * 128 + g * 16),
                 Bg + (size_t)row * 512 + koff + g * 16);
        }
    };

    load_chunk(0, 0);
    asm volatile("cp.async.commit_group;" ::: "memory");
    asm volatile("cp.async.wait_group 0;" ::: "memory");
    __syncthreads();

#pragma unroll 1
    for (int ck = 0; ck < NCHUNK; ck++) {
        const int cur = ck & 1;
        if (ck + 1 < NCHUNK) {
            load_chunk(ck + 1, cur ^ 1);
            asm volatile("cp.async.commit_group;" ::: "memory");
        }
        const uint32_t sA = sb + (cur ? SMA1 : SMA0);
        const uint32_t sB = sb + (cur ? SMB1 : SMB0);

#pragma unroll
        for (int kk = 0; kk < 4; kk++) {
            uint32_t a[2][4];
#pragma unroll
            for (int mt = 0; mt < 2; mt++) {
                int row  = wm * 32 + mt * 16 + a_r;
                int byte = row * 128 + (kk * 2 + a_kh) * 16;
                ldm_x4(a[mt], sA + (byte ^ ((byte >> 3) & 0x70)));
            }
#pragma unroll
            for (int ntp = 0; ntp < 4; ntp++) {
                int row  = wn * 64 + ntp * 16 + b_r;
                int byte = row * 128 + (kk * 2 + b_kh) * 16;
                uint32_t bbf[4];
                ldm_x4(bbf, sB + (byte ^ ((byte >> 3) & 0x70)));
#pragma unroll
                for (int mt = 0; mt < 2; mt++) {
                    mma16816(acc[mt][2 * ntp],     a[mt], bbf[0], bbf[1]);
                    mma16816(acc[mt][2 * ntp + 1], a[mt], bbf[2], bbf[3]);
                }
            }
        }
        if (ck + 1 < NCHUNK)
            asm volatile("cp.async.wait_group 0;" ::: "memory");
        __syncthreads();
    }

    // ---- epilogue ----
    float*  sd     = (float*)(smem + EP_SD);    // [128][4]
    float*  smin   = (float*)(smem + EP_MIN);   // [128]
    int*    scount = (int*)(smem + EP_CNT);     // [128]
    float2* sentry = (float2*)(smem + EP_ENT);  // [128][NSLOT]

    // phase 1: per-(row, warp-col-span) min
#pragma unroll
    for (int s = 0; s < 4; s++) {
        const int mt = s >> 1;
        const int ch = (s & 1) * 2;
        const int rl = wm * 32 + mt * 16 + (s & 1) * 8 + q;
        const float t1 = g_t1[m0 + rl];
        float bd = CUDART_INF_F;
#pragma unroll
        for (int nt = 0; nt < 8; nt++) {
            float d0 = __fsub_rn(t1, __fmul_rn(2.0f, acc[mt][nt][ch]));
            float d1 = __fsub_rn(t1, __fmul_rn(2.0f, acc[mt][nt][ch + 1]));
            bd = fminf(bd, fminf(d0, d1));
        }
#pragma unroll
        for (int o = 1; o <= 2; o <<= 1)
            bd = fminf(bd, __shfl_xor_sync(0xffffffffu, bd, o));
        if (qt == 0) sd[rl * 4 + wn] = bd;
    }
    __syncthreads();

    // phase 2: tile min per row -> g_pd, smem; reset counters
    if (tid < 128) {
        float bd = CUDART_INF_F;
#pragma unroll
        for (int w = 0; w < 4; w++) bd = fminf(bd, sd[tid * 4 + w]);
        g_pd[(size_t)(m0 + tid) * NBLK2 + nb] = bd;
        smin[tid]   = bd;
        scount[tid] = 0;
    }
    __syncthreads();

    // phase 3: threshold scan + candidate push
#pragma unroll
    for (int s = 0; s < 4; s++) {
        const int mt = s >> 1;
        const int ch = (s & 1) * 2;
        const int rl = wm * 32 + mt * 16 + (s & 1) * 8 + q;
        const float t1  = g_t1[m0 + rl];
        const float thr = smin[rl] + RESCREEN_THR;
#pragma unroll
        for (int nt = 0; nt < 8; nt++) {
            int c0 = wn * 64 + nt * 8 + qt * 2;
            float d0 = __fsub_rn(t1, __fmul_rn(2.0f, acc[mt][nt][ch]));
            float d1 = __fsub_rn(t1, __fmul_rn(2.0f, acc[mt][nt][ch + 1]));
            if (d0 <= thr) {
                int pos = atomicAdd(&scount[rl], 1);
                if (pos < NSLOT)
                    sentry[rl * NSLOT + pos] =
                        make_float2(d0, __int_as_float(n0 + c0));
            }
            if (d1 <= thr) {
                int pos = atomicAdd(&scount[rl], 1);
                if (pos < NSLOT)
                    sentry[rl * NSLOT + pos] =
                        make_float2(d1, __int_as_float(n0 + c0 + 1));
            }
        }
    }
    __syncthreads();

    // phase 4: write counts + all NSLOT slots (coalesced 32B/thread)
    if (tid < 128)
        g_ccnt[(size_t)(m0 + tid) * NBLK2 + nb] = scount[tid];
    {
        int rr = tid >> 2;              // 0..127
        int so = (tid & 3) * 4;         // slot offset 0,4,8,12
        const uint4* src = (const uint4*)(sentry + rr * NSLOT + so);
        uint4* dst = (uint4*)(g_cand + ((size_t)(m0 + rr) * NBLK2 + nb) * NSLOT + so);
        dst[0] = src[0];
        dst[1] = src[1];
    }
}

// ---------------------------------------------------------------------------
// K3: global TC-min per row.
// ---------------------------------------------------------------------------
__global__ void k_combine() {
    int row  = blockIdx.x * 8 + (threadIdx.x >> 5);
    int lane = threadIdx.x & 31;
    if (row >= NROWS) return;

    float bd = CUDART_INF_F;
    const float* pd = g_pd + (size_t)row * NBLK2;
#pragma unroll
    for (int x = lane; x < NBLK2; x += 32) bd = fminf(bd, pd[x]);
#pragma unroll
    for (int o = 16; o > 0; o >>= 1)
        bd = fminf(bd, __shfl_down_sync(0xffffffffu, bd, o));
    if (lane == 0) g_md[row] = bd;
}

// ---------------------------------------------------------------------------
// K3b: rescreen from candidate lists. Capture: any exact achiever col* has
// d_tc(col*) - tile_min_tc(its tile) <= 2*delta < THR, so it is in its tile's
// list (or the tile overflowed and is recomputed in full). Filter candidates
// by g_md + THR, exact fp32 fmaf dots, lexicographic (d, idx) min.
// One block (256 threads) per row.
// ---------------------------------------------------------------------------
__global__ void k_rescreen(const float* __restrict__ z,
                           const float* __restrict__ emb,
                           float* __restrict__ out, int out_size) {
    __shared__ float zr[KDIM];
    __shared__ float sbd[256];
    __shared__ int   sbi[256];
    __shared__ int   cl_col[1024];     // <= 64 cells * 16 slots
    __shared__ int   ovf[64];
    __shared__ int   cl_n, novf;
    const int row = blockIdx.x;
    const int tid = threadIdx.x;
    const int b = row >> 10, hw = row & 1023;
    zr[tid] = z[(size_t)b * 262144 + (size_t)tid * 1024 + hw];
    if (tid == 0) { cl_n = 0; novf = 0; }
    __syncthreads();

    const float t1  = g_t1[row];
    const float thr = g_md[row] + RESCREEN_THR;

    if (tid < NBLK2) {
        int cb  = tid;
        int cnt = g_ccnt[(size_t)row * NBLK2 + cb];
        if (cnt > NSLOT) {
            int p = atomicAdd(&novf, 1);
            ovf[p] = cb;
        } else {
            const float2* e = g_cand + ((size_t)row * NBLK2 + cb) * NSLOT;
            for (int i = 0; i < cnt; i++) {
                float2 v = e[i];
                if (v.x <= thr) {
                    int p = atomicAdd(&cl_n, 1);
                    cl_col[p] = __float_as_int(v.y);
                }
            }
        }
    }
    __syncthreads();

    float bd = CUDART_INF_F;
    int   bi = 0x7fffffff;
    // normal candidates
    for (int i = tid; i < cl_n; i += 256) {
        int col = cl_col[i];
        const float* e = emb + (size_t)col * KDIM;
        float s = 0.0f;
#pragma unroll 8
        for (int k = 0; k < KDIM; k++) s = fmaf(zr[k], e[k], s);
        float dex = __fsub_rn(t1, __fmul_rn(2.0f, s));
        if (dex < bd || (dex == bd && col < bi)) { bd = dex; bi = col; }
    }
    // overflowed tiles: recompute all 256 cols exactly (1 col per thread)
    for (int j = 0; j < novf; j++) {
        int col = ovf[j] * TCN + tid;
        const float* e = emb + (size_t)col * KDIM;
        float s = 0.0f;
#pragma unroll 8
        for (int k = 0; k < KDIM; k++) s = fmaf(zr[k], e[k], s);
        float dex = __fsub_rn(t1, __fmul_rn(2.0f, s));
        if (dex < bd || (dex == bd && col < bi)) { bd = dex; bi = col; }
    }

    sbd[tid] = bd; sbi[tid] = bi;
    __syncthreads();
#pragma unroll
    for (int o = 128; o > 0; o >>= 1) {
        if (tid < o) {
            float od = sbd[tid + o]; int oi = sbi[tid + o];
            if (od < sbd[tid] || (od == sbd[tid] && oi < sbi[tid])) {
                sbd[tid] = od; sbi[tid] = oi;
            }
        }
        __syncthreads();
    }
    if (tid == 0) {
        g_idx[row] = sbi[0];
        int pos = NZQ + 1 + row;
        if (pos < out_size) out[pos] = (float)sbi[0];
    }
}

// ---------------------------------------------------------------------------
// K4: z_q gather + STE output + per-block loss partials (exact fp32 emulation).
// ---------------------------------------------------------------------------
__global__ void k_out(const float* __restrict__ z, const float* __restrict__ emb,
                      float* __restrict__ out, int out_size) {
    int pos = blockIdx.x * 256 + threadIdx.x;
    double contrib = 0.0;
    if (pos < NZQ) {
        int b   = pos >> 18;
        int r   = pos & 262143;
        int c   = r >> 10;
        int hw  = r & 1023;
        int row = (b << 10) + hw;
        int idx = g_idx[row];
        float ztv   = z[pos];
        float zq    = emb[(size_t)idx * 256 + c];
        float delta = __fsub_rn(zq, ztv);
        if (pos < out_size) out[pos] = __fadd_rn(ztv, delta);
        contrib = (double)__fmul_rn(delta, delta);
    }
    __shared__ double s[256];
    s[threadIdx.x] = contrib;
    __syncthreads();
#pragma unroll
    for (int o = 128; o > 0; o >>= 1) {
        if (threadIdx.x < o) s[threadIdx.x] += s[threadIdx.x + o];
        __syncthreads();
    }
    if (threadIdx.x == 0) g_lpart[blockIdx.x] = s[0];
}

// ---------------------------------------------------------------------------
// K5: deterministic final loss. loss = fl(m + fl(0.25*m)), m = fl32(sum/NZQ).
// ---------------------------------------------------------------------------
__global__ void k_loss(float* __restrict__ out, int out_size) {
    __shared__ double s[256];
    double acc = 0.0;
    for (int x = threadIdx.x; x < NOUTBLOCKS; x += 256) acc += g_lpart[x];
    s[threadIdx.x] = acc;
    __syncthreads();
#pragma unroll
    for (int o = 128; o > 0; o >>= 1) {
        if (threadIdx.x < o) s[threadIdx.x] += s[threadIdx.x + o];
        __syncthreads();
    }
    if (threadIdx.x == 0 && NZQ < out_size) {
        float m = (float)(s[0] / (double)NZQ);
        out[NZQ] = __fadd_rn(m, __fmul_rn(0.25f, m));
    }
}

// ---------------------------------------------------------------------------
extern "C" void kernel_launch(void* const* d_in, const int* in_sizes, int n_in,
                              void* d_out, int out_size) {
    const float* z   = (const float*)d_in[0];   // [8,256,32,32]
    const float* emb = (const float*)d_in[1];   // [16384,256]
    float* out = (float*)d_out;

    cudaFuncSetAttribute(k_gemm_mma, cudaFuncAttributeMaxDynamicSharedMemorySize,
                         SM_TOTAL);

    k_prep<<<NROWS / 256, 256>>>(z);
    k_convB<<<(NE * KDIM) / 256, 256>>>(emb);
    {
        dim3 g(32, 8, 8);   // hw-tiles, c-tiles, b
        k_convA<<<g, dim3(32 * 32)>>>(z);
    }
    {
        dim3 g(NBLK2, MBLK2);   // 64 x 64
        k_gemm_mma<<<g, 512, SM_TOTAL>>>();
    }
    k_combine<<<NROWS / 8, 256>>>();
    k_rescreen<<<NROWS, 256>>>(z, emb, out, out_size);
    k_out<<<NOUTBLOCKS, 256>>>(z, emb, out, out_size);
    k_loss<<<1, 256>>>(out, out_size);
}

// round 15
// speedup vs baseline: 1.7511x; 1.7511x over previous
#include <cuda_runtime.h>
#include <cuda_bf16.h>
#include <math_constants.h>
#include <cstdint>

// Problem constants
#define NROWS 8192      // B*H*W = 8*32*32
#define NE    16384
#define KDIM  256
#define NCHUNK 4        // KDIM/64
#define TCM   128       // rows per CTA tile
#define TCN   256       // cols per CTA tile
#define NBLK2 (NE / TCN)    // 64
#define MBLK2 (NROWS / TCM) // 64
#define NZQ   2097152
#define NOUTBLOCKS (NZQ / 256)
// Screening threshold: worst-case deviation of reconstructed-bf16 screening d
// vs exact d: 1.4e-4 (bf16 inputs+TC, Cauchy-Schwarz) + 3.5e-5 (bf16 dot
// store). Capture condition needs THR > delta + 1.4e-4 = 3.2e-4. 6e-4 holds.
#define RESCREEN_THR 6e-4f

#define SWZ(x) ((x) ^ (((x) >> 3) & 0x70))

// GEMM smem: A chunks (128 rows x 128B) x2, B chunks (256 rows x 128B) x2
#define SMA0 0
#define SMA1 16384
#define SMB0 32768
#define SMB1 65536
#define SM_TOTAL 98304

// Scratch (device globals; no allocation allowed)
__device__ float  g_t1[NROWS];
__device__ float  g_pd[NROWS * 64];
__device__ float  g_md[NROWS];            // global TC-min per row
__device__ int    g_idx[NROWS];
__device__ double g_lpart[NOUTBLOCKS];
__device__ __align__(16) __nv_bfloat16 g_Aext[(size_t)NROWS * KDIM];   // 4 MB
__device__ __align__(16) __nv_bfloat16 g_Bext[(size_t)NE * KDIM];      // 8 MB
__device__ __align__(16) __nv_bfloat16 g_Db[(size_t)NROWS * NE];       // 256 MB bf16 dots

// ---------------- PTX helpers (all baseline ISA, legal on plain sm_100) ----
__device__ __forceinline__ uint32_t smem_u32(const void* p) {
    uint32_t a;
    asm("{ .reg .u64 t; cvta.to.shared.u64 t, %1; cvt.u32.u64 %0, t; }" : "=r"(a) : "l"(p));
    return a;
}
__device__ __forceinline__ void cp16(uint32_t d, const void* s) {
    asm volatile("cp.async.cg.shared.global [%0], [%1], 16;" :: "r"(d), "l"(s) : "memory");
}
__device__ __forceinline__ void ldm_x4(uint32_t* r, uint32_t a) {
    asm volatile("ldmatrix.sync.aligned.m8n8.x4.shared.b16 {%0,%1,%2,%3}, [%4];"
                 : "=r"(r[0]), "=r"(r[1]), "=r"(r[2]), "=r"(r[3]) : "r"(a));
}
__device__ __forceinline__ void mma16816(float* c, const uint32_t* a,
                                         uint32_t b0, uint32_t b1) {
    asm volatile(
        "mma.sync.aligned.m16n8k16.row.col.f32.bf16.bf16.f32 "
        "{%0,%1,%2,%3}, {%4,%5,%6,%7}, {%8,%9}, {%0,%1,%2,%3};"
        : "+f"(c[0]), "+f"(c[1]), "+f"(c[2]), "+f"(c[3])
        : "r"(a[0]), "r"(a[1]), "r"(a[2]), "r"(a[3]), "r"(b0), "r"(b1));
}

// ---------------------------------------------------------------------------
// K1: per-row ||z||^2.
// ---------------------------------------------------------------------------
__global__ void k_prep(const float* __restrict__ z) {
    int row = blockIdx.x * blockDim.x + threadIdx.x;
    if (row >= NROWS) return;
    int b  = row >> 10;
    int hw = row & 1023;
    const float* p = z + (size_t)b * 262144 + hw;
    float s = 0.0f;
#pragma unroll 8
    for (int c = 0; c < KDIM; c++) {
        float v = p[(size_t)c * 1024];
        s = fmaf(v, v, s);
    }
    g_t1[row] = s;
}

// ---------------------------------------------------------------------------
// K1b: RN-convert emb to bf16 (screening precision only; rescreen repairs).
// ---------------------------------------------------------------------------
__global__ void k_convB(const float* __restrict__ emb) {
    int t = blockIdx.x * 256 + threadIdx.x;
    if (t >= NE * KDIM) return;
    g_Bext[t] = __float2bfloat16(emb[t]);
}

// ---------------------------------------------------------------------------
// K1c: transpose z to row-major [row][k] and RN-convert to bf16.
// ---------------------------------------------------------------------------
__global__ void k_convA(const float* __restrict__ z) {
    __shared__ float s[32][33];
    int tx = threadIdx.x & 31, ty = threadIdx.x >> 5;
    int hw0 = blockIdx.x * 32, c0 = blockIdx.y * 32, b = blockIdx.z;
    s[ty][tx] = z[(size_t)b * 262144 + (size_t)(c0 + ty) * 1024 + hw0 + tx];
    __syncthreads();
    int r = (b << 10) + hw0 + ty;
    int c = c0 + tx;
    g_Aext[(size_t)r * KDIM + c] = __float2bfloat16(s[tx][ty]);
}

// ---------------------------------------------------------------------------
// K2: mma.sync bf16 GEMM (dot over K=256), screening pass.
// CTA 128x256, 512 threads = 16 warps (4m x 4n), warp tile 32x64.
// 4 K-chunks of 64 bf16 (=128B SW128 rows), cp.async double buffered.
// Epilogue: per-colblock f32 min -> g_pd; bf16 dot pairs stored DIRECTLY
// from the acc loop (no smem staging, no barriers between fragments —
// the R11-validated store pattern at half the bytes).
// ---------------------------------------------------------------------------
__global__ void __launch_bounds__(512, 1) k_gemm_mma() {
    extern __shared__ char smem[];
    const uint32_t sb = smem_u32(smem);
    const int tid  = threadIdx.x;
    const int lane = tid & 31;
    const int warp = tid >> 5;
    const int wm   = warp >> 2;         // 0..3: m block of 32
    const int wn   = warp & 3;          // 0..3: n block of 64
    const int q    = lane >> 2;         // quad id 0..7
    const int qt   = lane & 3;
    const int nb   = blockIdx.x;
    const int mb   = blockIdx.y;
    const int m0   = mb * TCM;
    const int n0   = nb * TCN;

    const char* Ag = (const char*)(g_Aext + (size_t)m0 * KDIM);
    const char* Bg = (const char*)(g_Bext + (size_t)n0 * KDIM);

    // ldmatrix lane address patterns
    const int a_r  = (lane & 7) + ((lane >> 3) & 1) * 8;   // row within m16
    const int a_kh = lane >> 4;                            // k-half
    const int b_r  = (lane & 7) + ((lane >> 4) & 1) * 8;   // row within n16 pair
    const int b_kh = (lane >> 3) & 1;                      // k-half

    float acc[2][8][4];
#pragma unroll
    for (int mt = 0; mt < 2; mt++)
#pragma unroll
        for (int nt = 0; nt < 8; nt++)
#pragma unroll
            for (int r = 0; r < 4; r++) acc[mt][nt][r] = 0.0f;

    // chunk loader: row stride is KDIM*2 = 512 bytes
    auto load_chunk = [&](int ck, int buf) {
        const int koff = ck * 128;
#pragma unroll
        for (int p = 0; p < 2; p++) {
            int idx = tid + p * 512;
            int row = idx >> 3, g = idx & 7;
            cp16(sb + (buf ? SMA1 : SMA0) + (uint32_t)SWZ(row * 128 + g * 16),
                 Ag + (size_t)row * 512 + koff + g * 16);
        }
#pragma unroll
        for (int p = 0; p < 4; p++) {
            int idx = tid + p * 512;
            int row = idx >> 3, g = idx & 7;
            cp16(sb + (buf ? SMB1 : SMB0) + (uint32_t)SWZ(row * 128 + g * 16),
                 Bg + (size_t)row * 512 + koff + g * 16);
        }
    };

    load_chunk(0, 0);
    asm volatile("cp.async.commit_group;" ::: "memory");
    asm volatile("cp.async.wait_group 0;" ::: "memory");
    __syncthreads();

#pragma unroll 1
    for (int ck = 0; ck < NCHUNK; ck++) {
        const int cur = ck & 1;
        if (ck + 1 < NCHUNK) {
            load_chunk(ck + 1, cur ^ 1);
            asm volatile("cp.async.commit_group;" ::: "memory");
        }
        const uint32_t sA = sb + (cur ? SMA1 : SMA0);
        const uint32_t sB = sb + (cur ? SMB1 : SMB0);

#pragma unroll
        for (int kk = 0; kk < 4; kk++) {
            uint32_t a[2][4];
#pragma unroll
            for (int mt = 0; mt < 2; mt++) {
                int row  = wm * 32 + mt * 16 + a_r;
                int byte = row * 128 + (kk * 2 + a_kh) * 16;
                ldm_x4(a[mt], sA + (byte ^ ((byte >> 3) & 0x70)));
            }
#pragma unroll
            for (int ntp = 0; ntp < 4; ntp++) {
                int row  = wn * 64 + ntp * 16 + b_r;
                int byte = row * 128 + (kk * 2 + b_kh) * 16;
                uint32_t bbf[4];
                ldm_x4(bbf, sB + (byte ^ ((byte >> 3) & 0x70)));
#pragma unroll
                for (int mt = 0; mt < 2; mt++) {
                    mma16816(acc[mt][2 * ntp],     a[mt], bbf[0], bbf[1]);
                    mma16816(acc[mt][2 * ntp + 1], a[mt], bbf[2], bbf[3]);
                }
            }
        }
        if (ck + 1 < NCHUNK)
            asm volatile("cp.async.wait_group 0;" ::: "memory");
        __syncthreads();
    }

    // ---- epilogue: f32 colblock min + direct bf16 dot-pair stores ----
    float* sd = (float*)smem;            // [128][4] floats (safe: post-sync)

#pragma unroll
    for (int s = 0; s < 4; s++) {
        const int mt = s >> 1;
        const int ch = (s & 1) * 2;                 // col pair (c0, c0+1), row rl
        const int rl = wm * 32 + mt * 16 + (s & 1) * 8 + q;
        const float t1 = g_t1[m0 + rl];
        float bd = CUDART_INF_F;
        __nv_bfloat16* drow = g_Db + (size_t)(m0 + rl) * NE + n0;
#pragma unroll
        for (int nt = 0; nt < 8; nt++) {
            int c0 = wn * 64 + nt * 8 + qt * 2;
            float d0 = __fsub_rn(t1, __fmul_rn(2.0f, acc[mt][nt][ch]));
            float d1 = __fsub_rn(t1, __fmul_rn(2.0f, acc[mt][nt][ch + 1]));
            bd = fminf(bd, fminf(d0, d1));
            // direct 4B store (c0 even -> aligned); sectors merge in L2
            *(__nv_bfloat162*)(drow + c0) =
                __floats2bfloat162_rn(acc[mt][nt][ch], acc[mt][nt][ch + 1]);
        }
#pragma unroll
        for (int o = 1; o <= 2; o <<= 1) {
            float od = __shfl_xor_sync(0xffffffffu, bd, o);
            bd = fminf(bd, od);
        }
        if (qt == 0) sd[rl * 4 + wn] = bd;
    }
    __syncthreads();

    if (tid < 128) {
        float bd = CUDART_INF_F;
#pragma unroll
        for (int w = 0; w < 4; w++) bd = fminf(bd, sd[tid * 4 + w]);
        g_pd[(size_t)(m0 + tid) * NBLK2 + nb] = bd;
    }
}

// ---------------------------------------------------------------------------
// K3: global TC-min per row (screening threshold base).
// ---------------------------------------------------------------------------
__global__ void k_combine() {
    int row  = blockIdx.x * 8 + (threadIdx.x >> 5);
    int lane = threadIdx.x & 31;
    if (row >= NROWS) return;

    float bd = CUDART_INF_F;
    const float* pd = g_pd + (size_t)row * NBLK2;
#pragma unroll
    for (int x = lane; x < NBLK2; x += 32) bd = fminf(bd, pd[x]);
#pragma unroll
    for (int o = 16; o > 0; o >>= 1)
        bd = fminf(bd, __shfl_down_sync(0xffffffffu, bd, o));
    if (lane == 0) g_md[row] = bd;
}

// ---------------------------------------------------------------------------
// K3b: rescreen on bf16 dots (byte-identical to the R12-validated version).
// Reconstructed screening d deviates <= 1.75e-4 from exact; THR covers
// capture. Exact fp32 recompute + lexicographic (d, idx) min =
// jnp.argmin first-occurrence. One block (256 threads) per row.
// ---------------------------------------------------------------------------
__global__ void k_rescreen(const float* __restrict__ z,
                           const float* __restrict__ emb,
                           float* __restrict__ out, int out_size) {
    __shared__ float zr[KDIM];
    __shared__ float sbd[256];
    __shared__ int   sbi[256];
    const int row = blockIdx.x;
    const int tid = threadIdx.x;
    const int b = row >> 10, hw = row & 1023;
    zr[tid] = z[(size_t)b * 262144 + (size_t)tid * 1024 + hw];
    __syncthreads();

    const float t1  = g_t1[row];
    const float thr = g_md[row] + RESCREEN_THR;
    const __nv_bfloat16* drow = g_Db + (size_t)row * NE;

    float bd = CUDART_INF_F;
    int   bi = 0x7fffffff;
#pragma unroll 1
    for (int base = tid * 8; base < NE; base += 2048) {
        uint4 v = *(const uint4*)(drow + base);
        const __nv_bfloat162* p2 = (const __nv_bfloat162*)&v;
#pragma unroll
        for (int j = 0; j < 8; j++) {
            float dot = __bfloat162float(((const __nv_bfloat16*)p2)[j]);
            float dv  = __fsub_rn(t1, __fmul_rn(2.0f, dot));
            if (dv <= thr) {
                int col = base + j;
                const float* e = emb + (size_t)col * KDIM;
                float s = 0.0f;
#pragma unroll 8
                for (int k = 0; k < KDIM; k++) s = fmaf(zr[k], e[k], s);
                float dex = __fsub_rn(t1, __fmul_rn(2.0f, s));
                if (dex < bd || (dex == bd && col < bi)) { bd = dex; bi = col; }
            }
        }
    }
    sbd[tid] = bd; sbi[tid] = bi;
    __syncthreads();
#pragma unroll
    for (int o = 128; o > 0; o >>= 1) {
        if (tid < o) {
            float od = sbd[tid + o]; int oi = sbi[tid + o];
            if (od < sbd[tid] || (od == sbd[tid] && oi < sbi[tid])) {
                sbd[tid] = od; sbi[tid] = oi;
            }
        }
        __syncthreads();
    }
    if (tid == 0) {
        g_idx[row] = sbi[0];
        int pos = NZQ + 1 + row;
        if (pos < out_size) out[pos] = (float)sbi[0];
    }
}

// ---------------------------------------------------------------------------
// K4: z_q gather + STE output + per-block loss partials (exact fp32 emulation).
// ---------------------------------------------------------------------------
__global__ void k_out(const float* __restrict__ z, const float* __restrict__ emb,
                      float* __restrict__ out, int out_size) {
    int pos = blockIdx.x * 256 + threadIdx.x;
    double contrib = 0.0;
    if (pos < NZQ) {
        int b   = pos >> 18;
        int r   = pos & 262143;
        int c   = r >> 10;
        int hw  = r & 1023;
        int row = (b << 10) + hw;
        int idx = g_idx[row];
        float ztv   = z[pos];
        float zq    = emb[(size_t)idx * 256 + c];
        float delta = __fsub_rn(zq, ztv);
        if (pos < out_size) out[pos] = __fadd_rn(ztv, delta);
        contrib = (double)__fmul_rn(delta, delta);
    }
    __shared__ double s[256];
    s[threadIdx.x] = contrib;
    __syncthreads();
#pragma unroll
    for (int o = 128; o > 0; o >>= 1) {
        if (threadIdx.x < o) s[threadIdx.x] += s[threadIdx.x + o];
        __syncthreads();
    }
    if (threadIdx.x == 0) g_lpart[blockIdx.x] = s[0];
}

// ---------------------------------------------------------------------------
// K5: deterministic final loss. loss = fl(m + fl(0.25*m)), m = fl32(sum/NZQ).
// ---------------------------------------------------------------------------
__global__ void k_loss(float* __restrict__ out, int out_size) {
    __shared__ double s[256];
    double acc = 0.0;
    for (int x = threadIdx.x; x < NOUTBLOCKS; x += 256) acc += g_lpart[x];
    s[threadIdx.x] = acc;
    __syncthreads();
#pragma unroll
    for (int o = 128; o > 0; o >>= 1) {
        if (threadIdx.x < o) s[threadIdx.x] += s[threadIdx.x + o];
        __syncthreads();
    }
    if (threadIdx.x == 0 && NZQ < out_size) {
        float m = (float)(s[0] / (double)NZQ);
        out[NZQ] = __fadd_rn(m, __fmul_rn(0.25f, m));
    }
}

// ---------------------------------------------------------------------------
extern "C" void kernel_launch(void* const* d_in, const int* in_sizes, int n_in,
                              void* d_out, int out_size) {
    const float* z   = (const float*)d_in[0];   // [8,256,32,32]
    const float* emb = (const float*)d_in[1];   // [16384,256]
    float* out = (float*)d_out;

    cudaFuncSetAttribute(k_gemm_mma, cudaFuncAttributeMaxDynamicSharedMemorySize,
                         SM_TOTAL);

    k_prep<<<NROWS / 256, 256>>>(z);
    k_convB<<<(NE * KDIM) / 256, 256>>>(emb);
    {
        dim3 g(32, 8, 8);   // hw-tiles, c-tiles, b
        k_convA<<<g, dim3(32 * 32)>>>(z);
    }
    {
        dim3 g(NBLK2, MBLK2);   // 64 x 64
        k_gemm_mma<<<g, 512, SM_TOTAL>>>();
    }
    k_combine<<<NROWS / 8, 256>>>();
    k_rescreen<<<NROWS, 256>>>(z, emb, out, out_size);
    k_out<<<NOUTBLOCKS, 256>>>(z, emb, out, out_size);
    k_loss<<<1, 256>>>(out, out_size);
}